// round 12
// baseline (speedup 1.0000x reference)
#include <cuda_runtime.h>
#include <cstdint>

#define B_ 64
#define T_ 1024
#define I_ 256
#define H_ 512

typedef unsigned long long u64;

// ---------------- packed f32x2 helpers (sm_103a) ----------------
__device__ __forceinline__ u64 pack2(float lo, float hi) {
    u64 r; asm("mov.b64 %0, {%1, %2};" : "=l"(r) : "f"(lo), "f"(hi)); return r;
}
__device__ __forceinline__ u64 fma2(u64 a, u64 b, u64 c) {
    u64 d; asm("fma.rn.f32x2 %0, %1, %2, %3;" : "=l"(d) : "l"(a), "l"(b), "l"(c)); return d;
}
__device__ __forceinline__ u64 add2(u64 a, u64 b) {
    u64 d; asm("add.rn.f32x2 %0, %1, %2;" : "=l"(d) : "l"(a), "l"(b)); return d;
}
__device__ __forceinline__ float2 unpack2(u64 v) {
    float2 r; asm("mov.b64 {%0, %1}, %2;" : "=f"(r.x), "=f"(r.y) : "l"(v)); return r;
}

// ---------------- static device scratch ----------------
// Projections stored transposed: [t][j][b]  -> index (t*H_ + j)*B_ + b
__device__ float g_xz[(size_t)T_ * H_ * B_];
__device__ float g_xr[(size_t)T_ * H_ * B_];
__device__ float g_xh[(size_t)T_ * H_ * B_];
// Hidden state double buffer, layout [b][j]
__device__ float g_h[2][B_ * H_];
// r*h exchange, DUPLICATED layout [b][2j] (each value stored twice, adjacent)
__device__ float g_rh2[B_ * 2 * H_];
// Per-batch-group barrier: 8 slots, 128B apart; reset by proj kernel each launch.
struct __align__(128) BarSlot { unsigned count; unsigned gen; unsigned pad[30]; };
__device__ BarSlot g_bar[8];

// ---------------- per-batch-group barrier (16 CTAs), precomputed generation ----
// Barrier instance with pre-gen g0 releases gen = g0+1. No leading gen load.
__device__ __forceinline__ void group_sync_(int bg, unsigned g0) {
    __syncthreads();
    if (threadIdx.x == 0) {
        unsigned* cnt  = &g_bar[bg].count;
        unsigned* genp = &g_bar[bg].gen;
        unsigned old, v;
        asm volatile("atom.release.gpu.add.u32 %0, [%1], %2;"
                     : "=r"(old) : "l"(cnt), "r"(1u) : "memory");
        if (old == 15u) {
            asm volatile("st.relaxed.gpu.u32 [%0], %1;" :: "l"(cnt), "r"(0u) : "memory");
            asm volatile("st.release.gpu.u32 [%0], %1;" :: "l"(genp), "r"(g0 + 1u) : "memory");
        } else {
            do {
                asm volatile("ld.acquire.gpu.u32 %0, [%1];" : "=r"(v) : "l"(genp) : "memory");
            } while (v < g0 + 1u);
        }
    }
    __syncthreads();
}

// =================================================================================
// Projection GEMM (proven) + barrier-slot reset (replay safety)
// =================================================================================
__global__ __launch_bounds__(256) void gru_proj_kernel(
    const float* __restrict__ xs,
    const float* __restrict__ Wz, const float* __restrict__ Wr, const float* __restrict__ Wh,
    const float* __restrict__ bz, const float* __restrict__ br, const float* __restrict__ bh)
{
    __shared__ float As[8 * 132];
    __shared__ float Bs[8 * 132];

    if (blockIdx.x == 0 && blockIdx.y == 0 && blockIdx.z == 0 && threadIdx.x < 8) {
        g_bar[threadIdx.x].count = 0u;
        g_bar[threadIdx.x].gen   = 0u;
    }

    const int g = blockIdx.z;
    const float* W    = (g == 0) ? Wz : (g == 1) ? Wr : Wh;
    const float* bias = (g == 0) ? bz : (g == 1) ? br : bh;
    float*       out  = (g == 0) ? g_xz : (g == 1) ? g_xr : g_xh;

    const int m0 = blockIdx.x * 128;
    const int n0 = blockIdx.y * 128;
    const int tid = (int)threadIdx.x;

    const int tx = tid & 15;
    const int ty = tid >> 4;

    const int arow = tid >> 1, aseg = tid & 1;
    const int brow = tid >> 5, bcol4 = (tid & 31) * 4;

    u64 acc2[8][4];
#pragma unroll
    for (int i = 0; i < 8; ++i)
#pragma unroll
        for (int j = 0; j < 4; ++j) acc2[i][j] = 0ull;

    for (int k0 = 0; k0 < I_; k0 += 8) {
        float4 av = *(const float4*)&xs[(size_t)(m0 + arow) * I_ + k0 + aseg * 4];
        float4 bv = *(const float4*)&W[(size_t)(k0 + brow) * H_ + n0 + bcol4];
        __syncthreads();
        As[(aseg * 4 + 0) * 132 + arow] = av.x;
        As[(aseg * 4 + 1) * 132 + arow] = av.y;
        As[(aseg * 4 + 2) * 132 + arow] = av.z;
        As[(aseg * 4 + 3) * 132 + arow] = av.w;
        *(float4*)&Bs[brow * 132 + bcol4] = bv;
        __syncthreads();
#pragma unroll
        for (int kk = 0; kk < 8; ++kk) {
            float a[8];
            float4 a0 = *(const float4*)&As[kk * 132 + ty * 8];
            float4 a1 = *(const float4*)&As[kk * 132 + ty * 8 + 4];
            ulonglong2 bq0 = *(const ulonglong2*)&Bs[kk * 132 + tx * 8];
            ulonglong2 bq1 = *(const ulonglong2*)&Bs[kk * 132 + tx * 8 + 4];
            a[0]=a0.x; a[1]=a0.y; a[2]=a0.z; a[3]=a0.w;
            a[4]=a1.x; a[5]=a1.y; a[6]=a1.z; a[7]=a1.w;
            u64 bp[4] = { bq0.x, bq0.y, bq1.x, bq1.y };
#pragma unroll
            for (int i = 0; i < 8; ++i) {
                u64 ap = pack2(a[i], a[i]);
#pragma unroll
                for (int j = 0; j < 4; ++j) acc2[i][j] = fma2(ap, bp[j], acc2[i][j]);
            }
        }
    }

#pragma unroll
    for (int j = 0; j < 4; ++j) {
        const int n = n0 + tx * 8 + 2 * j;
        const float bi0 = bias[n], bi1 = bias[n + 1];
#pragma unroll
        for (int i = 0; i < 8; ++i) {
            const int m = m0 + ty * 8 + i;
            const int t = m & (T_ - 1);
            const int b = m >> 10;
            float2 v = unpack2(acc2[i][j]);
            out[(size_t)(t * H_ + n) * B_ + b]     = v.x + bi0;
            out[(size_t)(t * H_ + n + 1) * B_ + b] = v.y + bi1;
        }
    }
}

// =================================================================================
// Persistent recurrence: 128 CTAs = 8 batch-groups x 16 col-groups, 256 thr, 1/SM.
// CTA owns 8 batches x 32 h-columns. Phase A: r only. Phase B: z + cand (rh
// streamed from global dup buffer; h stays in smem all step).
// =================================================================================
#define NB_CTA 8
#define NC_CTA 32
#define HS_S 520               // h_s[bl*520 + k]; bank = (8b + lane)&31
#define WS_S 100               // w_s[k*100 + c], c 0..95; quad = (25k + c/4)&7
#define SMEM_FLOATS (NB_CTA * HS_S + H_ * WS_S)
#define SMEM_BYTES  (SMEM_FLOATS * 4)

__device__ __forceinline__ float sigmoidf_(float x) {
    return 1.0f / (1.0f + expf(-x));
}

#define RSTAGE64(arr, N, M, lane)                                            \
    {                                                                        \
        const bool hi_ = ((lane) & (M)) != 0;                                \
        _Pragma("unroll")                                                    \
        for (int i_ = 0; i_ < (N); ++i_) {                                   \
            u64 send_ = hi_ ? arr[i_] : arr[i_ + (N)];                       \
            u64 recv_ = __shfl_xor_sync(0xffffffffu, send_, (M));            \
            u64 keep_ = hi_ ? arr[i_ + (N)] : arr[i_];                       \
            arr[i_] = add2(keep_, recv_);                                    \
        }                                                                    \
    }

// Stage 8-batch h slice: 1024 float4, 4 per thread, LDG-batched.
__device__ __forceinline__ void stage_h_(float* h_s, const float4* __restrict__ src, int tid) {
    float4 v[4];
#pragma unroll
    for (int u = 0; u < 4; ++u)
        v[u] = __ldcg(src + tid + u * 256);
#pragma unroll
    for (int u = 0; u < 4; ++u) {
        const int i = tid + u * 256;
        const int bl = i >> 7;
        const int k4 = (i & 127) << 2;
        *(float4*)&h_s[bl * HS_S + k4] = v[u];
    }
}

__global__ __launch_bounds__(256, 1) void gru_rec_kernel(
    const float* __restrict__ Wz, const float* __restrict__ Wr, const float* __restrict__ Wh,
    float* __restrict__ out)
{
    extern __shared__ float smem[];
    float* h_s = smem;                         // NB_CTA * 520
    float* w_s = h_s + NB_CTA * HS_S;          // H_ * 100

    const int tid  = (int)threadIdx.x;
    const int w    = tid >> 5;
    const int lane = tid & 31;
    const int bg   = (int)blockIdx.x >> 4;     // batch group 0..7
    const int cg   = (int)blockIdx.x & 15;     // col group 0..15
    const int col0 = cg * NC_CTA;
    const int bc0  = bg * NB_CTA;

    // ---- one-time: 96 weight columns (32 z | 32 r | 32 cand) ----
    for (int i = tid; i < H_ * 96; i += 256) {
        const int k = i / 96, c = i % 96;
        const float* W = (c < 32) ? Wz : (c < 64) ? Wr : Wh;
        w_s[k * WS_S + c] = W[(size_t)(I_ + k) * H_ + col0 + (c & 31)];
    }

    // ---- phase A mappings (16-acc tree: lane l -> idx (l>>1)&15, parity l&1) ----
    const int cpA  = (lane >> 4) & 1;
    const int bA   = (lane >> 1) & 7;
    const int parA = lane & 1;
    const int jA   = 4 * w + 2 * cpA + parA;   // r-col local 0..31
    // ---- phase B mappings (32-acc tree: lane l -> idx l: q=l>>3, b=l&7) ----
    const int qB  = lane >> 3;                 // 0,1 = z pairs; 2,3 = cand pairs
    const int bB  = lane & 7;
    const int jz0 = 4 * w + 2 * (qB & 1);      // col pair base (even)

#pragma unroll 1
    for (int t = 0; t < T_; ++t) {
        // ---- stage h slice (layout [local b][k]); t==0: h = 0 ----
        __syncthreads();   // h_s free (covers w_s staging on iter 0)
        if (t == 0) {
#pragma unroll
            for (int u = 0; u < 4; ++u) {
                const int i = tid + u * 256;
                const int bl = i >> 7, k4 = (i & 127) << 2;
                *(float4*)&h_s[bl * HS_S + k4] = make_float4(0.f, 0.f, 0.f, 0.f);
            }
        } else {
            stage_h_(h_s, (const float4*)&g_h[t & 1][(size_t)bc0 * H_], tid);
        }
        float xrA = __ldcg(&g_xr[((size_t)t * H_ + col0 + jA) * B_ + bc0 + bA]);
        __syncthreads();

        // ---- phase A: r dots only; warp = 2 col-pairs x 8 batches, k-split 32 ----
        u64 accA[16];                          // idx = cp*8 + b
#pragma unroll
        for (int i = 0; i < 16; ++i) accA[i] = 0ull;
#pragma unroll 4
        for (int it = 0; it < 16; ++it) {
            const int k = lane + (it << 5);
            ulonglong2 wq = *(const ulonglong2*)&w_s[k * WS_S + 32 + 4 * w];
            float hv[8];
#pragma unroll
            for (int b = 0; b < 8; ++b) hv[b] = h_s[b * HS_S + k];
#pragma unroll
            for (int b = 0; b < 8; ++b) {
                u64 hb = pack2(hv[b], hv[b]);
                accA[b]     = fma2(wq.x, hb, accA[b]);
                accA[8 + b] = fma2(wq.y, hb, accA[8 + b]);
            }
        }
        RSTAGE64(accA, 8, 16, lane)
        RSTAGE64(accA, 4,  8, lane)
        RSTAGE64(accA, 2,  4, lane)
        RSTAGE64(accA, 1,  2, lane)
        accA[0] = add2(accA[0], __shfl_xor_sync(0xffffffffu, accA[0], 1));

        {
            float2 dp = unpack2(accA[0]);
            const float dot  = parA ? dp.y : dp.x;
            const float r    = sigmoidf_(xrA + dot);
            const float hold = h_s[bA * HS_S + col0 + jA];
            const float rh   = r * hold;
            __stcg((float2*)&g_rh2[(size_t)(bc0 + bA) * (2 * H_) + 2 * (col0 + jA)],
                   make_float2(rh, rh));
        }
        // prefetch phase-B gate operands + hold (independent of rh exchange)
        const size_t xiB = ((size_t)t * H_ + col0 + jz0) * B_ + bc0 + bB;
        float xz0 = __ldcg(&g_xz[xiB]);
        float xz1 = __ldcg(&g_xz[xiB + B_]);
        float xh0 = __ldcg(&g_xh[xiB]);
        float xh1 = __ldcg(&g_xh[xiB + B_]);
        const float hold0 = h_s[bB * HS_S + col0 + jz0];
        const float hold1 = h_s[bB * HS_S + col0 + jz0 + 1];
        group_sync_(bg, 2u * (unsigned)t);

        // ---- phase B: z dots (from smem h) + cand dots (rh streamed, dup) ----
        u64 acc[32];                           // idx = q*8 + b: q0,1 z; q2,3 cand
#pragma unroll
        for (int i = 0; i < 32; ++i) acc[i] = 0ull;
        const u64* rhrow = (const u64*)&g_rh2[(size_t)bc0 * (2 * H_)];
#pragma unroll 4
        for (int it = 0; it < 16; ++it) {
            const int k = lane + (it << 5);
            ulonglong2 wqz = *(const ulonglong2*)&w_s[k * WS_S + 4 * w];
            ulonglong2 wqc = *(const ulonglong2*)&w_s[k * WS_S + 64 + 4 * w];
            u64 rq[8];
#pragma unroll
            for (int b = 0; b < 8; ++b)
                rq[b] = __ldcg(rhrow + (size_t)b * H_ + k);
            float hv[8];
#pragma unroll
            for (int b = 0; b < 8; ++b) hv[b] = h_s[b * HS_S + k];
#pragma unroll
            for (int b = 0; b < 8; ++b) {
                u64 hb = pack2(hv[b], hv[b]);
                acc[b]      = fma2(wqz.x, hb, acc[b]);
                acc[8 + b]  = fma2(wqz.y, hb, acc[8 + b]);
                acc[16 + b] = fma2(wqc.x, rq[b], acc[16 + b]);
                acc[24 + b] = fma2(wqc.y, rq[b], acc[24 + b]);
            }
        }
        RSTAGE64(acc, 16, 16, lane)
        RSTAGE64(acc,  8,  8, lane)
        RSTAGE64(acc,  4,  4, lane)
        RSTAGE64(acc,  2,  2, lane)
        RSTAGE64(acc,  1,  1, lane)
        // lane l holds idx l; pair z (lanes <16) with cand (lanes >=16)
        u64 other = __shfl_xor_sync(0xffffffffu, acc[0], 16);

        if (lane < 16) {
            float2 zd = unpack2(acc[0]);
            float2 cd = unpack2(other);
            const float z0 = sigmoidf_(xz0 + zd.x);
            const float z1 = sigmoidf_(xz1 + zd.y);
            const float h0 = tanhf(xh0 + cd.x);
            const float h1 = tanhf(xh1 + cd.y);
            const float hn0 = fmaf(z0, h0 - hold0, hold0);
            const float hn1 = fmaf(z1, h1 - hold1, hold1);
            const int gb = bc0 + bB;
            float2 hv2 = make_float2(hn0, hn1);
            *(float2*)&out[(size_t)gb * T_ * H_ + (size_t)t * H_ + col0 + jz0] = hv2;
            __stcg((float2*)&g_h[(t + 1) & 1][(size_t)gb * H_ + col0 + jz0], hv2);
            if (t == T_ - 1)
                *(float2*)&out[(size_t)B_ * T_ * H_ + (size_t)gb * H_ + col0 + jz0] = hv2;
        }
        group_sync_(bg, 2u * (unsigned)t + 1u);
    }
}

// =================================================================================
extern "C" void kernel_launch(void* const* d_in, const int* in_sizes, int n_in,
                              void* d_out, int out_size) {
    const float* xs = (const float*)d_in[0];
    const float* Wz = (const float*)d_in[1];
    const float* bz = (const float*)d_in[2];
    const float* Wr = (const float*)d_in[3];
    const float* br = (const float*)d_in[4];
    const float* Wh = (const float*)d_in[5];
    const float* bh = (const float*)d_in[6];
    float* out = (float*)d_out;

    cudaFuncSetAttribute(gru_rec_kernel,
                         cudaFuncAttributeMaxDynamicSharedMemorySize, SMEM_BYTES);

    dim3 pg(T_ * B_ / 128, H_ / 128, 3);
    gru_proj_kernel<<<pg, 256>>>(xs, Wz, Wr, Wh, bz, br, bh);

    gru_rec_kernel<<<128, 256, SMEM_BYTES>>>(Wz, Wr, Wh, out);
}

// round 13
// speedup vs baseline: 1.2391x; 1.2391x over previous
#include <cuda_runtime.h>
#include <cstdint>

#define B_ 64
#define T_ 1024
#define I_ 256
#define H_ 512

typedef unsigned long long u64;

// ---------------- packed f32x2 helpers (sm_103a) ----------------
__device__ __forceinline__ u64 pack2(float lo, float hi) {
    u64 r; asm("mov.b64 %0, {%1, %2};" : "=l"(r) : "f"(lo), "f"(hi)); return r;
}
__device__ __forceinline__ u64 fma2(u64 a, u64 b, u64 c) {
    u64 d; asm("fma.rn.f32x2 %0, %1, %2, %3;" : "=l"(d) : "l"(a), "l"(b), "l"(c)); return d;
}
__device__ __forceinline__ u64 add2(u64 a, u64 b) {
    u64 d; asm("add.rn.f32x2 %0, %1, %2;" : "=l"(d) : "l"(a), "l"(b)); return d;
}
__device__ __forceinline__ float2 unpack2(u64 v) {
    float2 r; asm("mov.b64 {%0, %1}, %2;" : "=f"(r.x), "=f"(r.y) : "l"(v)); return r;
}

// ---------------- static device scratch ----------------
// Projections stored transposed: [t][j][b]  -> index (t*H_ + j)*B_ + b
__device__ float g_xz[(size_t)T_ * H_ * B_];
__device__ float g_xr[(size_t)T_ * H_ * B_];
__device__ float g_xh[(size_t)T_ * H_ * B_];
// Hidden state double buffer + r*h exchange, layout [b][j]
__device__ float g_h[2][B_ * H_];
__device__ float g_rh[B_ * H_];
// Per-batch-group barrier: 8 slots, 128B apart; reset by proj kernel each launch.
struct __align__(128) BarSlot { unsigned count; unsigned gen; unsigned pad[30]; };
__device__ BarSlot g_bar[8];

// ---------------- split barrier (16 CTAs/group), precomputed generation ----------
// Barrier with pre-gen g0 releases gen = g0+1 at the 16th arrival (no gen preload).
__device__ __forceinline__ bool group_arrive_(int bg, unsigned g0) {
    __syncthreads();
    bool rel = false;
    if (threadIdx.x == 0) {
        unsigned old;
        asm volatile("atom.release.gpu.add.u32 %0, [%1], %2;"
                     : "=r"(old) : "l"(&g_bar[bg].count), "r"(1u) : "memory");
        if (old == 15u) {
            asm volatile("st.relaxed.gpu.u32 [%0], %1;"
                         :: "l"(&g_bar[bg].count), "r"(0u) : "memory");
            asm volatile("st.release.gpu.u32 [%0], %1;"
                         :: "l"(&g_bar[bg].gen), "r"(g0 + 1u) : "memory");
            rel = true;
        }
    }
    return rel;
}
__device__ __forceinline__ void group_wait_(int bg, unsigned g0, bool rel) {
    if (threadIdx.x == 0 && !rel) {
        unsigned v;
        do {
            asm volatile("ld.acquire.gpu.u32 %0, [%1];"
                         : "=r"(v) : "l"(&g_bar[bg].gen) : "memory");
        } while (v < g0 + 1u);
    }
    __syncthreads();
}

// =================================================================================
// Projection GEMM (proven) + barrier-slot reset (replay safety)
// =================================================================================
__global__ __launch_bounds__(256) void gru_proj_kernel(
    const float* __restrict__ xs,
    const float* __restrict__ Wz, const float* __restrict__ Wr, const float* __restrict__ Wh,
    const float* __restrict__ bz, const float* __restrict__ br, const float* __restrict__ bh)
{
    __shared__ float As[8 * 132];
    __shared__ float Bs[8 * 132];

    if (blockIdx.x == 0 && blockIdx.y == 0 && blockIdx.z == 0 && threadIdx.x < 8) {
        g_bar[threadIdx.x].count = 0u;
        g_bar[threadIdx.x].gen   = 0u;
    }

    const int g = blockIdx.z;
    const float* W    = (g == 0) ? Wz : (g == 1) ? Wr : Wh;
    const float* bias = (g == 0) ? bz : (g == 1) ? br : bh;
    float*       out  = (g == 0) ? g_xz : (g == 1) ? g_xr : g_xh;

    const int m0 = blockIdx.x * 128;
    const int n0 = blockIdx.y * 128;
    const int tid = (int)threadIdx.x;

    const int tx = tid & 15;
    const int ty = tid >> 4;

    const int arow = tid >> 1, aseg = tid & 1;
    const int brow = tid >> 5, bcol4 = (tid & 31) * 4;

    u64 acc2[8][4];
#pragma unroll
    for (int i = 0; i < 8; ++i)
#pragma unroll
        for (int j = 0; j < 4; ++j) acc2[i][j] = 0ull;

    for (int k0 = 0; k0 < I_; k0 += 8) {
        float4 av = *(const float4*)&xs[(size_t)(m0 + arow) * I_ + k0 + aseg * 4];
        float4 bv = *(const float4*)&W[(size_t)(k0 + brow) * H_ + n0 + bcol4];
        __syncthreads();
        As[(aseg * 4 + 0) * 132 + arow] = av.x;
        As[(aseg * 4 + 1) * 132 + arow] = av.y;
        As[(aseg * 4 + 2) * 132 + arow] = av.z;
        As[(aseg * 4 + 3) * 132 + arow] = av.w;
        *(float4*)&Bs[brow * 132 + bcol4] = bv;
        __syncthreads();
#pragma unroll
        for (int kk = 0; kk < 8; ++kk) {
            float a[8];
            float4 a0 = *(const float4*)&As[kk * 132 + ty * 8];
            float4 a1 = *(const float4*)&As[kk * 132 + ty * 8 + 4];
            ulonglong2 bq0 = *(const ulonglong2*)&Bs[kk * 132 + tx * 8];
            ulonglong2 bq1 = *(const ulonglong2*)&Bs[kk * 132 + tx * 8 + 4];
            a[0]=a0.x; a[1]=a0.y; a[2]=a0.z; a[3]=a0.w;
            a[4]=a1.x; a[5]=a1.y; a[6]=a1.z; a[7]=a1.w;
            u64 bp[4] = { bq0.x, bq0.y, bq1.x, bq1.y };
#pragma unroll
            for (int i = 0; i < 8; ++i) {
                u64 ap = pack2(a[i], a[i]);
#pragma unroll
                for (int j = 0; j < 4; ++j) acc2[i][j] = fma2(ap, bp[j], acc2[i][j]);
            }
        }
    }

#pragma unroll
    for (int j = 0; j < 4; ++j) {
        const int n = n0 + tx * 8 + 2 * j;
        const float bi0 = bias[n], bi1 = bias[n + 1];
#pragma unroll
        for (int i = 0; i < 8; ++i) {
            const int m = m0 + ty * 8 + i;
            const int t = m & (T_ - 1);
            const int b = m >> 10;
            float2 v = unpack2(acc2[i][j]);
            out[(size_t)(t * H_ + n) * B_ + b]     = v.x + bi0;
            out[(size_t)(t * H_ + n + 1) * B_ + b] = v.y + bi1;
        }
    }
}

// =================================================================================
// Persistent recurrence: 128 CTAs = 8 batch-groups x 16 col-groups, 256 thr, 1/SM.
// CTA owns 8 batches x 32 h-columns. Phase A1: r dots -> rh store -> ARRIVE.
// Phase A2 (overlaps barrier wait): z dots from h_s. WAIT -> stage rh -> phase B.
// =================================================================================
#define NB_CTA 8
#define NC_CTA 32
#define HS_S 520               // h_s[bl*520 + k]; bank = (8b + lane)&31
#define WS_S 100               // w_s[k*100 + c], c 0..95; quad = (25k + c/4)&7
#define ZS_S 33
#define SMEM_FLOATS (NB_CTA * HS_S + H_ * WS_S + NB_CTA * ZS_S * 2)
#define SMEM_BYTES  (SMEM_FLOATS * 4)

__device__ __forceinline__ float sigmoidf_(float x) {
    return 1.0f / (1.0f + expf(-x));
}

#define RSTAGE64(arr, N, M, lane)                                            \
    {                                                                        \
        const bool hi_ = ((lane) & (M)) != 0;                                \
        _Pragma("unroll")                                                    \
        for (int i_ = 0; i_ < (N); ++i_) {                                   \
            u64 send_ = hi_ ? arr[i_] : arr[i_ + (N)];                       \
            u64 recv_ = __shfl_xor_sync(0xffffffffu, send_, (M));            \
            u64 keep_ = hi_ ? arr[i_ + (N)] : arr[i_];                       \
            arr[i_] = add2(keep_, recv_);                                    \
        }                                                                    \
    }

// 16-acc dot block: cols [cbase, cbase+4) x 8 batches, k-split 32.
// After tree: lane l holds pair for col 4w+2cp+par, batch (l>>1)&7.
#define DOT16(accv, cbase)                                                   \
    _Pragma("unroll")                                                        \
    for (int i = 0; i < 16; ++i) accv[i] = 0ull;                             \
    _Pragma("unroll 4")                                                      \
    for (int it = 0; it < 16; ++it) {                                        \
        const int k = lane + (it << 5);                                      \
        ulonglong2 wq = *(const ulonglong2*)&w_s[k * WS_S + (cbase)];        \
        float hv[8];                                                         \
        _Pragma("unroll")                                                    \
        for (int b = 0; b < 8; ++b) hv[b] = h_s[b * HS_S + k];               \
        _Pragma("unroll")                                                    \
        for (int b = 0; b < 8; ++b) {                                        \
            u64 hb = pack2(hv[b], hv[b]);                                    \
            accv[b]     = fma2(wq.x, hb, accv[b]);                           \
            accv[8 + b] = fma2(wq.y, hb, accv[8 + b]);                       \
        }                                                                    \
    }                                                                        \
    RSTAGE64(accv, 8, 16, lane)                                              \
    RSTAGE64(accv, 4,  8, lane)                                              \
    RSTAGE64(accv, 2,  4, lane)                                              \
    RSTAGE64(accv, 1,  2, lane)                                              \
    accv[0] = add2(accv[0], __shfl_xor_sync(0xffffffffu, accv[0], 1));

// Stage 8-batch slice: 1024 float4, 4 per thread, LDG-batched.
__device__ __forceinline__ void stage_h_(float* h_s, const float4* __restrict__ src, int tid) {
    float4 v[4];
#pragma unroll
    for (int u = 0; u < 4; ++u)
        v[u] = __ldcg(src + tid + u * 256);
#pragma unroll
    for (int u = 0; u < 4; ++u) {
        const int i = tid + u * 256;
        const int bl = i >> 7;
        const int k4 = (i & 127) << 2;
        *(float4*)&h_s[bl * HS_S + k4] = v[u];
    }
}

__global__ __launch_bounds__(256, 1) void gru_rec_kernel(
    const float* __restrict__ Wz, const float* __restrict__ Wr, const float* __restrict__ Wh,
    float* __restrict__ out)
{
    extern __shared__ float smem[];
    float* h_s  = smem;                        // NB_CTA * 520
    float* w_s  = h_s + NB_CTA * HS_S;         // H_ * 100
    float* z_s  = w_s + H_ * WS_S;             // 8 x 33
    float* hk_s = z_s + NB_CTA * ZS_S;         // 8 x 33

    const int tid  = (int)threadIdx.x;
    const int w    = tid >> 5;
    const int lane = tid & 31;
    const int bg   = (int)blockIdx.x >> 4;     // batch group 0..7
    const int cg   = (int)blockIdx.x & 15;     // col group 0..15
    const int col0 = cg * NC_CTA;
    const int bc0  = bg * NB_CTA;

    // ---- one-time: 96 weight columns (32 z | 32 r | 32 cand) ----
    for (int i = tid; i < H_ * 96; i += 256) {
        const int k = i / 96, c = i % 96;
        const float* W = (c < 32) ? Wz : (c < 64) ? Wr : Wh;
        w_s[k * WS_S + c] = W[(size_t)(I_ + k) * H_ + col0 + (c & 31)];
    }

    // ---- lane mappings for the 16-acc tree (all three phases) ----
    const int cpA  = (lane >> 4) & 1;
    const int bA   = (lane >> 1) & 7;
    const int parA = lane & 1;
    const int jA   = 4 * w + 2 * cpA + parA;   // local col 0..31

#pragma unroll 1
    for (int t = 0; t < T_; ++t) {
        // ---- stage h slice (layout [local b][k]); t==0: h = 0 ----
        __syncthreads();   // h_s free (covers w_s staging on iter 0)
        if (t == 0) {
#pragma unroll
            for (int u = 0; u < 4; ++u) {
                const int i = tid + u * 256;
                const int bl = i >> 7, k4 = (i & 127) << 2;
                *(float4*)&h_s[bl * HS_S + k4] = make_float4(0.f, 0.f, 0.f, 0.f);
            }
        } else {
            stage_h_(h_s, (const float4*)&g_h[t & 1][(size_t)bc0 * H_], tid);
        }
        const size_t xi = ((size_t)t * H_ + col0 + jA) * B_ + bc0 + bA;
        float xrA = __ldcg(&g_xr[xi]);
        float xzA = __ldcg(&g_xz[xi]);
        float xhB = __ldcg(&g_xh[xi]);
        __syncthreads();

        // ---- phase A1: r dots (weight slots 32..63) -> rh -> ARRIVE ----
        u64 accA[16];
        DOT16(accA, 32 + 4 * w)
        {
            float2 dp = unpack2(accA[0]);
            const float dot  = parA ? dp.y : dp.x;
            const float r    = sigmoidf_(xrA + dot);
            const float hold = h_s[bA * HS_S + col0 + jA];
            hk_s[bA * ZS_S + jA] = hold;
            __stcg(&g_rh[(size_t)(bc0 + bA) * H_ + col0 + jA], r * hold);
        }
        bool rel1 = group_arrive_(bg, 2u * (unsigned)t);

        // ---- phase A2 (overlaps barrier wait): z dots (slots 0..31) ----
        u64 accZ[16];
        DOT16(accZ, 4 * w)
        {
            float2 dp = unpack2(accZ[0]);
            const float dot = parA ? dp.y : dp.x;
            z_s[bA * ZS_S + jA] = sigmoidf_(xzA + dot);
        }
        group_wait_(bg, 2u * (unsigned)t, rel1);

        // ---- stage r*h slice (overwrites h_s; z already extracted) ----
        stage_h_(h_s, (const float4*)&g_rh[(size_t)bc0 * H_], tid);
        __syncthreads();

        // ---- phase B: candidate dots (slots 64..95) ----
        u64 accB[16];
        DOT16(accB, 64 + 4 * w)
        {
            float2 pr = unpack2(accB[0]);
            const float cand = parA ? pr.y : pr.x;
            const float z    = z_s[bA * ZS_S + jA];
            const float hold = hk_s[bA * ZS_S + jA];
            const float ht = tanhf(xhB + cand);
            const float hn = fmaf(z, ht - hold, hold);
            const int gb = bc0 + bA;
            out[(size_t)gb * T_ * H_ + (size_t)t * H_ + col0 + jA] = hn;
            __stcg(&g_h[(t + 1) & 1][(size_t)gb * H_ + col0 + jA], hn);
            if (t == T_ - 1)
                out[(size_t)B_ * T_ * H_ + (size_t)gb * H_ + col0 + jA] = hn;
        }
        bool rel2 = group_arrive_(bg, 2u * (unsigned)t + 1u);
        group_wait_(bg, 2u * (unsigned)t + 1u, rel2);
    }
}

// =================================================================================
extern "C" void kernel_launch(void* const* d_in, const int* in_sizes, int n_in,
                              void* d_out, int out_size) {
    const float* xs = (const float*)d_in[0];
    const float* Wz = (const float*)d_in[1];
    const float* bz = (const float*)d_in[2];
    const float* Wr = (const float*)d_in[3];
    const float* br = (const float*)d_in[4];
    const float* Wh = (const float*)d_in[5];
    const float* bh = (const float*)d_in[6];
    float* out = (float*)d_out;

    cudaFuncSetAttribute(gru_rec_kernel,
                         cudaFuncAttributeMaxDynamicSharedMemorySize, SMEM_BYTES);

    dim3 pg(T_ * B_ / 128, H_ / 128, 3);
    gru_proj_kernel<<<pg, 256>>>(xs, Wz, Wr, Wh, bz, br, bh);

    gru_rec_kernel<<<128, 256, SMEM_BYTES>>>(Wz, Wr, Wh, out);
}

// round 14
// speedup vs baseline: 1.2449x; 1.0047x over previous
#include <cuda_runtime.h>
#include <cstdint>

#define B_ 64
#define T_ 1024
#define I_ 256
#define H_ 512

typedef unsigned long long u64;

// ---------------- packed f32x2 helpers (sm_103a) ----------------
__device__ __forceinline__ u64 pack2(float lo, float hi) {
    u64 r; asm("mov.b64 %0, {%1, %2};" : "=l"(r) : "f"(lo), "f"(hi)); return r;
}
__device__ __forceinline__ u64 fma2(u64 a, u64 b, u64 c) {
    u64 d; asm("fma.rn.f32x2 %0, %1, %2, %3;" : "=l"(d) : "l"(a), "l"(b), "l"(c)); return d;
}
__device__ __forceinline__ u64 add2(u64 a, u64 b) {
    u64 d; asm("add.rn.f32x2 %0, %1, %2;" : "=l"(d) : "l"(a), "l"(b)); return d;
}
__device__ __forceinline__ float2 unpack2(u64 v) {
    float2 r; asm("mov.b64 {%0, %1}, %2;" : "=f"(r.x), "=f"(r.y) : "l"(v)); return r;
}

// ---------------- static device scratch ----------------
// Projections stored transposed: [t][j][b]  -> index (t*H_ + j)*B_ + b
__device__ float g_xz[(size_t)T_ * H_ * B_];
__device__ float g_xr[(size_t)T_ * H_ * B_];
__device__ float g_xh[(size_t)T_ * H_ * B_];
// Hidden state double buffer + r*h exchange, layout [b][j]
__device__ float g_h[2][B_ * H_];
__device__ float g_rh[B_ * H_];
// Per-batch-group barrier: 8 slots, 128B apart; reset by proj kernel each launch.
struct __align__(128) BarSlot { unsigned count; unsigned gen; unsigned pad[30]; };
__device__ BarSlot g_bar[8];

// ---------------- split barrier (16 CTAs/group), precomputed generation ----------
__device__ __forceinline__ bool group_arrive_(int bg, unsigned g0) {
    __syncthreads();
    bool rel = false;
    if (threadIdx.x == 0) {
        unsigned old;
        asm volatile("atom.release.gpu.add.u32 %0, [%1], %2;"
                     : "=r"(old) : "l"(&g_bar[bg].count), "r"(1u) : "memory");
        if (old == 15u) {
            asm volatile("st.relaxed.gpu.u32 [%0], %1;"
                         :: "l"(&g_bar[bg].count), "r"(0u) : "memory");
            asm volatile("st.release.gpu.u32 [%0], %1;"
                         :: "l"(&g_bar[bg].gen), "r"(g0 + 1u) : "memory");
            rel = true;
        }
    }
    return rel;
}
__device__ __forceinline__ void group_wait_(int bg, unsigned g0, bool rel) {
    if (threadIdx.x == 0 && !rel) {
        unsigned v;
        do {
            asm volatile("ld.acquire.gpu.u32 %0, [%1];"
                         : "=r"(v) : "l"(&g_bar[bg].gen) : "memory");
        } while (v < g0 + 1u);
    }
    __syncthreads();
}

// =================================================================================
// Projection GEMM (proven) + barrier-slot reset (replay safety)
// =================================================================================
__global__ __launch_bounds__(256) void gru_proj_kernel(
    const float* __restrict__ xs,
    const float* __restrict__ Wz, const float* __restrict__ Wr, const float* __restrict__ Wh,
    const float* __restrict__ bz, const float* __restrict__ br, const float* __restrict__ bh)
{
    __shared__ float As[8 * 132];
    __shared__ float Bs[8 * 132];

    if (blockIdx.x == 0 && blockIdx.y == 0 && blockIdx.z == 0 && threadIdx.x < 8) {
        g_bar[threadIdx.x].count = 0u;
        g_bar[threadIdx.x].gen   = 0u;
    }

    const int g = blockIdx.z;
    const float* W    = (g == 0) ? Wz : (g == 1) ? Wr : Wh;
    const float* bias = (g == 0) ? bz : (g == 1) ? br : bh;
    float*       out  = (g == 0) ? g_xz : (g == 1) ? g_xr : g_xh;

    const int m0 = blockIdx.x * 128;
    const int n0 = blockIdx.y * 128;
    const int tid = (int)threadIdx.x;

    const int tx = tid & 15;
    const int ty = tid >> 4;

    const int arow = tid >> 1, aseg = tid & 1;
    const int brow = tid >> 5, bcol4 = (tid & 31) * 4;

    u64 acc2[8][4];
#pragma unroll
    for (int i = 0; i < 8; ++i)
#pragma unroll
        for (int j = 0; j < 4; ++j) acc2[i][j] = 0ull;

    for (int k0 = 0; k0 < I_; k0 += 8) {
        float4 av = *(const float4*)&xs[(size_t)(m0 + arow) * I_ + k0 + aseg * 4];
        float4 bv = *(const float4*)&W[(size_t)(k0 + brow) * H_ + n0 + bcol4];
        __syncthreads();
        As[(aseg * 4 + 0) * 132 + arow] = av.x;
        As[(aseg * 4 + 1) * 132 + arow] = av.y;
        As[(aseg * 4 + 2) * 132 + arow] = av.z;
        As[(aseg * 4 + 3) * 132 + arow] = av.w;
        *(float4*)&Bs[brow * 132 + bcol4] = bv;
        __syncthreads();
#pragma unroll
        for (int kk = 0; kk < 8; ++kk) {
            float a[8];
            float4 a0 = *(const float4*)&As[kk * 132 + ty * 8];
            float4 a1 = *(const float4*)&As[kk * 132 + ty * 8 + 4];
            ulonglong2 bq0 = *(const ulonglong2*)&Bs[kk * 132 + tx * 8];
            ulonglong2 bq1 = *(const ulonglong2*)&Bs[kk * 132 + tx * 8 + 4];
            a[0]=a0.x; a[1]=a0.y; a[2]=a0.z; a[3]=a0.w;
            a[4]=a1.x; a[5]=a1.y; a[6]=a1.z; a[7]=a1.w;
            u64 bp[4] = { bq0.x, bq0.y, bq1.x, bq1.y };
#pragma unroll
            for (int i = 0; i < 8; ++i) {
                u64 ap = pack2(a[i], a[i]);
#pragma unroll
                for (int j = 0; j < 4; ++j) acc2[i][j] = fma2(ap, bp[j], acc2[i][j]);
            }
        }
    }

#pragma unroll
    for (int j = 0; j < 4; ++j) {
        const int n = n0 + tx * 8 + 2 * j;
        const float bi0 = bias[n], bi1 = bias[n + 1];
#pragma unroll
        for (int i = 0; i < 8; ++i) {
            const int m = m0 + ty * 8 + i;
            const int t = m & (T_ - 1);
            const int b = m >> 10;
            float2 v = unpack2(acc2[i][j]);
            out[(size_t)(t * H_ + n) * B_ + b]     = v.x + bi0;
            out[(size_t)(t * H_ + n + 1) * B_ + b] = v.y + bi1;
        }
    }
}

// =================================================================================
// Persistent recurrence: 128 CTAs = 8 batch-groups x 16 col-groups, 256 thr, 1/SM.
// CTA owns 8 batches x 32 h-columns. Phase A1: r dots -> rh -> ARRIVE.
// Phase A2 (overlaps barrier wait): z dots. WAIT -> stage rh -> phase B.
// Weights split into even-k / odd-k planes so paired-k LDS.64 h loads keep
// the weight LDS.128 pattern conflict-free.
// =================================================================================
#define NB_CTA 8
#define NC_CTA 32
#define HS_S 520               // h_s[bl*520 + k]; LDS.64 bank = (8b + 2lane)&31
#define WS_S 100               // per-plane: w[k2*100 + c]; bank start 4*lane
#define ZS_S 33
#define SMEM_FLOATS (NB_CTA * HS_S + 2 * (H_/2) * WS_S + NB_CTA * ZS_S * 2)
#define SMEM_BYTES  (SMEM_FLOATS * 4)

__device__ __forceinline__ float sigmoidf_(float x) {
    return 1.0f / (1.0f + expf(-x));
}

#define RSTAGE64(arr, N, M, lane)                                            \
    {                                                                        \
        const bool hi_ = ((lane) & (M)) != 0;                                \
        _Pragma("unroll")                                                    \
        for (int i_ = 0; i_ < (N); ++i_) {                                   \
            u64 send_ = hi_ ? arr[i_] : arr[i_ + (N)];                       \
            u64 recv_ = __shfl_xor_sync(0xffffffffu, send_, (M));            \
            u64 keep_ = hi_ ? arr[i_ + (N)] : arr[i_];                       \
            arr[i_] = add2(keep_, recv_);                                    \
        }                                                                    \
    }

// 16-acc dot block, paired-k: each iteration handles k=2*(lane+32it) and k+1.
// Tree is k-partition agnostic (full 32-lane sum). After tree: lane l holds
// pair for col cbase..+2cp+par (cp=(l>>4)&1, par=l&1), batch (l>>1)&7.
#define DOT16(accv, cbase)                                                   \
    _Pragma("unroll")                                                        \
    for (int i = 0; i < 16; ++i) accv[i] = 0ull;                             \
    _Pragma("unroll 4")                                                      \
    for (int it = 0; it < 8; ++it) {                                         \
        const int k2 = lane + (it << 5);                                     \
        ulonglong2 wq0 = *(const ulonglong2*)&w_ev[k2 * WS_S + (cbase)];     \
        ulonglong2 wq1 = *(const ulonglong2*)&w_od[k2 * WS_S + (cbase)];     \
        float2 hv2[8];                                                       \
        _Pragma("unroll")                                                    \
        for (int b = 0; b < 8; ++b)                                          \
            hv2[b] = *(const float2*)&h_s[b * HS_S + 2 * k2];                \
        _Pragma("unroll")                                                    \
        for (int b = 0; b < 8; ++b) {                                        \
            u64 hb0 = pack2(hv2[b].x, hv2[b].x);                             \
            u64 hb1 = pack2(hv2[b].y, hv2[b].y);                             \
            accv[b]     = fma2(wq0.x, hb0, accv[b]);                         \
            accv[b]     = fma2(wq1.x, hb1, accv[b]);                         \
            accv[8 + b] = fma2(wq0.y, hb0, accv[8 + b]);                     \
            accv[8 + b] = fma2(wq1.y, hb1, accv[8 + b]);                     \
        }                                                                    \
    }                                                                        \
    RSTAGE64(accv, 8, 16, lane)                                              \
    RSTAGE64(accv, 4,  8, lane)                                              \
    RSTAGE64(accv, 2,  4, lane)                                              \
    RSTAGE64(accv, 1,  2, lane)                                              \
    accv[0] = add2(accv[0], __shfl_xor_sync(0xffffffffu, accv[0], 1));

// Stage 8-batch slice: 1024 float4, 4 per thread, LDG-batched.
__device__ __forceinline__ void stage_h_(float* h_s, const float4* __restrict__ src, int tid) {
    float4 v[4];
#pragma unroll
    for (int u = 0; u < 4; ++u)
        v[u] = __ldcg(src + tid + u * 256);
#pragma unroll
    for (int u = 0; u < 4; ++u) {
        const int i = tid + u * 256;
        const int bl = i >> 7;
        const int k4 = (i & 127) << 2;
        *(float4*)&h_s[bl * HS_S + k4] = v[u];
    }
}

__global__ __launch_bounds__(256, 1) void gru_rec_kernel(
    const float* __restrict__ Wz, const float* __restrict__ Wr, const float* __restrict__ Wh,
    float* __restrict__ out)
{
    extern __shared__ float smem[];
    float* h_s  = smem;                        // NB_CTA * 520
    float* w_ev = h_s + NB_CTA * HS_S;         // 256 * 100 (even k)
    float* w_od = w_ev + (H_/2) * WS_S;        // 256 * 100 (odd k)
    float* z_s  = w_od + (H_/2) * WS_S;        // 8 x 33
    float* hk_s = z_s + NB_CTA * ZS_S;         // 8 x 33

    const int tid  = (int)threadIdx.x;
    const int w    = tid >> 5;
    const int lane = tid & 31;
    const int bg   = (int)blockIdx.x >> 4;     // batch group 0..7
    const int cg   = (int)blockIdx.x & 15;     // col group 0..15
    const int col0 = cg * NC_CTA;
    const int bc0  = bg * NB_CTA;

    // ---- one-time: 96 weight columns (32 z | 32 r | 32 cand), split by k parity --
    for (int i = tid; i < H_ * 96; i += 256) {
        const int k = i / 96, c = i % 96;
        const float* W = (c < 32) ? Wz : (c < 64) ? Wr : Wh;
        float* dst = (k & 1) ? w_od : w_ev;
        dst[(k >> 1) * WS_S + c] = W[(size_t)(I_ + k) * H_ + col0 + (c & 31)];
    }

    // ---- lane mappings for the 16-acc tree (all three phases) ----
    const int cpA  = (lane >> 4) & 1;
    const int bA   = (lane >> 1) & 7;
    const int parA = lane & 1;
    const int jA   = 4 * w + 2 * cpA + parA;   // local col 0..31

    // ---- software-pipelined x-gate operands ----
    const size_t x0 = (size_t)(col0 + jA) * B_ + bc0 + bA;
    const size_t xstep = (size_t)H_ * B_;
    float xr_c = __ldcg(&g_xr[x0]);
    float xz_c = __ldcg(&g_xz[x0]);
    float xh_c = __ldcg(&g_xh[x0]);

#pragma unroll 1
    for (int t = 0; t < T_; ++t) {
        // ---- stage h slice (layout [local b][k]); t==0: h = 0 ----
        __syncthreads();   // h_s free (covers w staging on iter 0)
        if (t == 0) {
#pragma unroll
            for (int u = 0; u < 4; ++u) {
                const int i = tid + u * 256;
                const int bl = i >> 7, k4 = (i & 127) << 2;
                *(float4*)&h_s[bl * HS_S + k4] = make_float4(0.f, 0.f, 0.f, 0.f);
            }
        } else {
            stage_h_(h_s, (const float4*)&g_h[t & 1][(size_t)bc0 * H_], tid);
        }
        __syncthreads();

        // ---- phase A1: r dots (col slots 32..63) -> rh -> ARRIVE ----
        u64 accA[16];
        DOT16(accA, 32 + 4 * w)
        {
            float2 dp = unpack2(accA[0]);
            const float dot  = parA ? dp.y : dp.x;
            const float r    = sigmoidf_(xr_c + dot);
            const float hold = h_s[bA * HS_S + col0 + jA];
            hk_s[bA * ZS_S + jA] = hold;
            __stcg(&g_rh[(size_t)(bc0 + bA) * H_ + col0 + jA], r * hold);
        }
        bool rel1 = group_arrive_(bg, 2u * (unsigned)t);

        // ---- phase A2 (overlaps barrier wait): z dots (slots 0..31) ----
        u64 accZ[16];
        DOT16(accZ, 4 * w)
        {
            float2 dp = unpack2(accZ[0]);
            const float dot = parA ? dp.y : dp.x;
            z_s[bA * ZS_S + jA] = sigmoidf_(xz_c + dot);
        }
        group_wait_(bg, 2u * (unsigned)t, rel1);

        // ---- stage r*h slice (overwrites h_s; z already extracted) ----
        stage_h_(h_s, (const float4*)&g_rh[(size_t)bc0 * H_], tid);
        __syncthreads();

        // ---- phase B: candidate dots (slots 64..95) ----
        u64 accB[16];
        DOT16(accB, 64 + 4 * w)
        {
            float2 pr = unpack2(accB[0]);
            const float cand = parA ? pr.y : pr.x;
            const float z    = z_s[bA * ZS_S + jA];
            const float hold = hk_s[bA * ZS_S + jA];
            const float ht = tanhf(xh_c + cand);
            const float hn = fmaf(z, ht - hold, hold);
            const int gb = bc0 + bA;
            out[(size_t)gb * T_ * H_ + (size_t)t * H_ + col0 + jA] = hn;
            __stcg(&g_h[(t + 1) & 1][(size_t)gb * H_ + col0 + jA], hn);
            if (t == T_ - 1)
                out[(size_t)B_ * T_ * H_ + (size_t)gb * H_ + col0 + jA] = hn;
        }
        // prefetch next step's gate operands under the barrier-2 shadow
        if (t + 1 < T_) {
            const size_t xn = x0 + (size_t)(t + 1) * xstep;
            xr_c = __ldcg(&g_xr[xn]);
            xz_c = __ldcg(&g_xz[xn]);
            xh_c = __ldcg(&g_xh[xn]);
        }
        bool rel2 = group_arrive_(bg, 2u * (unsigned)t + 1u);
        group_wait_(bg, 2u * (unsigned)t + 1u, rel2);
    }
}

// =================================================================================
extern "C" void kernel_launch(void* const* d_in, const int* in_sizes, int n_in,
                              void* d_out, int out_size) {
    const float* xs = (const float*)d_in[0];
    const float* Wz = (const float*)d_in[1];
    const float* bz = (const float*)d_in[2];
    const float* Wr = (const float*)d_in[3];
    const float* br = (const float*)d_in[4];
    const float* Wh = (const float*)d_in[5];
    const float* bh = (const float*)d_in[6];
    float* out = (float*)d_out;

    cudaFuncSetAttribute(gru_rec_kernel,
                         cudaFuncAttributeMaxDynamicSharedMemorySize, SMEM_BYTES);

    dim3 pg(T_ * B_ / 128, H_ / 128, 3);
    gru_proj_kernel<<<pg, 256>>>(xs, Wz, Wr, Wh, bz, br, bh);

    gru_rec_kernel<<<128, 256, SMEM_BYTES>>>(Wz, Wr, Wh, out);
}